// round 1
// baseline (speedup 1.0000x reference)
#include <cuda_runtime.h>
#include <math.h>
#include <stdint.h>

// Problem constants
#define BB 4
#define TTT 2048
#define DM 512
#define DI 1024
#define DS 16
#define DCONV 4
#define MROWS (BB*TTT)   // 8192

// Scratch (allocation-free rule: __device__ globals)
__device__ float g_xs   [(size_t)MROWS*DI];
__device__ float g_res  [(size_t)MROWS*DI];
__device__ float g_xc   [(size_t)MROWS*DI];
__device__ float g_delta[(size_t)MROWS*DI];
__device__ float g_Bm   [(size_t)MROWS*DS];
__device__ float g_Cm   [(size_t)MROWS*DS];
__device__ float g_y    [(size_t)MROWS*DI];

// ---------------------------------------------------------------------------
// Generic NT GEMM:  C[M,N] = A[M,K] * B[N,K]^T   (all row-major)
// EPI: 0 = plain store to C1
//      1 = split store: n < N/2 -> C1[m, n], else C2[m, n-N/2]   (in_proj)
//      2 = softplus(acc + bias[n]) -> C1                          (dt_proj)
//      3 = B source concat (B1 rows 0..15, B2 rows 16..31),
//          output split C1 (n<16) / C2 (n>=16)                    (b/c proj)
// ---------------------------------------------------------------------------
template<int BM, int BN, int BK, int TM, int TN, int EPI>
__global__ void gemm_nt(const float* __restrict__ A,
                        const float* __restrict__ B1,
                        const float* __restrict__ B2,
                        float* __restrict__ C1,
                        float* __restrict__ C2,
                        const float* __restrict__ bias,
                        int M, int N, int K)
{
    constexpr int NT_THREADS = (BM/TM) * (BN/TN);
    __shared__ float As[BK][BM + 1];
    __shared__ float Bs[BK][BN + 1];

    const int tid = threadIdx.x;
    const int tx = tid % (BN / TN);
    const int ty = tid / (BN / TN);
    const int m0 = blockIdx.y * BM;
    const int n0 = blockIdx.x * BN;

    float acc[TM][TN];
#pragma unroll
    for (int i = 0; i < TM; ++i)
#pragma unroll
        for (int j = 0; j < TN; ++j) acc[i][j] = 0.f;

    for (int k0 = 0; k0 < K; k0 += BK) {
        // Load A tile (BM x BK)
        for (int i = tid; i < BM * BK; i += NT_THREADS) {
            int m = i / BK, k = i % BK;
            As[k][m] = A[(size_t)(m0 + m) * K + k0 + k];
        }
        // Load B tile (BN x BK)
        for (int i = tid; i < BN * BK; i += NT_THREADS) {
            int n = i / BK, k = i % BK;
            int gn = n0 + n;
            const float* Brow;
            if (EPI == 3) {
                Brow = (gn < DS) ? (B1 + (size_t)gn * K)
                                 : (B2 + (size_t)(gn - DS) * K);
            } else {
                Brow = B1 + (size_t)gn * K;
            }
            Bs[k][n] = Brow[k0 + k];
        }
        __syncthreads();

#pragma unroll
        for (int k = 0; k < BK; ++k) {
            float ra[TM], rb[TN];
#pragma unroll
            for (int i = 0; i < TM; ++i) ra[i] = As[k][ty * TM + i];
#pragma unroll
            for (int j = 0; j < TN; ++j) rb[j] = Bs[k][tx * TN + j];
#pragma unroll
            for (int i = 0; i < TM; ++i)
#pragma unroll
                for (int j = 0; j < TN; ++j)
                    acc[i][j] = fmaf(ra[i], rb[j], acc[i][j]);
        }
        __syncthreads();
    }

    // Epilogue
#pragma unroll
    for (int i = 0; i < TM; ++i) {
#pragma unroll
        for (int j = 0; j < TN; ++j) {
            int m = m0 + ty * TM + i;
            int n = n0 + tx * TN + j;
            float v = acc[i][j];
            if (EPI == 0) {
                C1[(size_t)m * N + n] = v;
            } else if (EPI == 1) {
                int half = N / 2;
                if (n < half) C1[(size_t)m * half + n] = v;
                else          C2[(size_t)m * half + (n - half)] = v;
            } else if (EPI == 2) {
                v += bias[n];
                C1[(size_t)m * N + n] = (v > 20.f) ? v : log1pf(expf(v));
            } else { // EPI == 3
                if (n < DS) C1[(size_t)m * DS + n] = v;
                else        C2[(size_t)m * DS + (n - DS)] = v;
            }
        }
    }
}

// ---------------------------------------------------------------------------
// Causal depthwise conv1d (width 4) + bias + SiLU:  g_xs -> g_xc
// ---------------------------------------------------------------------------
__global__ void conv_silu_kernel(const float* __restrict__ xs,
                                 const float* __restrict__ w,   // [DI,1,4]
                                 const float* __restrict__ bias,
                                 float* __restrict__ out)
{
    size_t i = (size_t)blockIdx.x * blockDim.x + threadIdx.x;
    if (i >= (size_t)MROWS * DI) return;
    int d  = (int)(i & (DI - 1));
    int bt = (int)(i >> 10);
    int t  = bt & (TTT - 1);

    float acc = bias[d];
    const float* wd = w + d * DCONV;
#pragma unroll
    for (int k = 0; k < DCONV; ++k) {
        int tt = t - (DCONV - 1) + k;
        if (tt >= 0) acc = fmaf(wd[k], xs[i + (size_t)(tt - t) * DI], acc);
    }
    out[i] = acc * (1.f / (1.f + expf(-acc)));
}

// ---------------------------------------------------------------------------
// Selective scan. 16 lanes per (b,d) channel; lane n owns state h[n].
// Fused: y = (sum_n h*C + x*D) * silu(res)
// 256 threads/block -> 16 channels/block; grid = 4096/16 = 256 blocks.
// ---------------------------------------------------------------------------
__global__ void scan_kernel(const float* __restrict__ delta,
                            const float* __restrict__ Bm,
                            const float* __restrict__ Cm,
                            const float* __restrict__ xc,
                            const float* __restrict__ res,
                            const float* __restrict__ A_log,
                            const float* __restrict__ Dv,
                            float* __restrict__ y)
{
    const int sub = threadIdx.x >> 4;        // channel slot within block [0,16)
    const int n   = threadIdx.x & 15;        // state index
    const int gch = blockIdx.x * 16 + sub;   // global channel [0, 4096)
    const int b = gch >> 10;
    const int d = gch & (DI - 1);

    const float Acoef = -__expf(A_log[d * DS + n]);
    const float Dval  = Dv[d];

    const size_t rowbase = (size_t)b * TTT;
    const float* dp = delta + rowbase * DI + d;
    const float* xp = xc    + rowbase * DI + d;
    const float* rp = res   + rowbase * DI + d;
    const float* Bp = Bm    + rowbase * DS + n;
    const float* Cp = Cm    + rowbase * DS + n;
    float*       yp = y     + rowbase * DI + d;

    float h = 0.f;
    for (int t = 0; t < TTT; ++t) {
        const size_t od = (size_t)t * DI;
        const size_t os = (size_t)t * DS;
        float dlt = dp[od];
        float xv  = xp[od];
        float Bn  = Bp[os];
        float Cn  = Cp[os];

        float dA = __expf(dlt * Acoef);
        h = fmaf(dA, h, (dlt * Bn) * xv);

        float p = h * Cn;
        p += __shfl_xor_sync(0xffffffffu, p, 8);
        p += __shfl_xor_sync(0xffffffffu, p, 4);
        p += __shfl_xor_sync(0xffffffffu, p, 2);
        p += __shfl_xor_sync(0xffffffffu, p, 1);

        if (n == 0) {
            float r = rp[od];
            float gate = r * (1.f / (1.f + expf(-r)));
            yp[od] = (p + xv * Dval) * gate;
        }
    }
}

// ---------------------------------------------------------------------------
extern "C" void kernel_launch(void* const* d_in, const int* in_sizes, int n_in,
                              void* d_out, int out_size)
{
    const float* x        = (const float*)d_in[0];
    const float* in_w     = (const float*)d_in[1];
    const float* conv_w   = (const float*)d_in[2];
    const float* conv_b   = (const float*)d_in[3];
    const float* b_w      = (const float*)d_in[4];
    const float* c_w      = (const float*)d_in[5];
    const float* dt_w     = (const float*)d_in[6];
    const float* dt_b     = (const float*)d_in[7];
    const float* A_log    = (const float*)d_in[8];
    const float* Dvec     = (const float*)d_in[9];
    const float* out_w    = (const float*)d_in[10];
    float* out            = (float*)d_out;

    float *xs, *res, *xc, *delta, *Bmp, *Cmp, *yb;
    cudaGetSymbolAddress((void**)&xs,    g_xs);
    cudaGetSymbolAddress((void**)&res,   g_res);
    cudaGetSymbolAddress((void**)&xc,    g_xc);
    cudaGetSymbolAddress((void**)&delta, g_delta);
    cudaGetSymbolAddress((void**)&Bmp,   g_Bm);
    cudaGetSymbolAddress((void**)&Cmp,   g_Cm);
    cudaGetSymbolAddress((void**)&yb,    g_y);

    // 1) in_proj: [8192,512] x [2048,512]^T -> split xs/res
    {
        dim3 grid(2 * DI / 64, MROWS / 64);
        gemm_nt<64, 64, 16, 4, 4, 1><<<grid, 256>>>(
            x, in_w, nullptr, xs, res, nullptr, MROWS, 2 * DI, DM);
    }
    // 2) causal depthwise conv + SiLU
    {
        size_t total = (size_t)MROWS * DI;
        conv_silu_kernel<<<(unsigned)((total + 255) / 256), 256>>>(
            xs, conv_w, conv_b, xc);
    }
    // 3) dt_proj + softplus: [8192,1024] x [1024,1024]^T
    {
        dim3 grid(DI / 64, MROWS / 64);
        gemm_nt<64, 64, 16, 4, 4, 2><<<grid, 256>>>(
            xc, dt_w, nullptr, delta, nullptr, dt_b, MROWS, DI, DI);
    }
    // 4) B/C proj (concat N=32): [8192,1024] x [32,1024]^T
    {
        dim3 grid(1, MROWS / 64);
        gemm_nt<64, 32, 16, 4, 2, 3><<<grid, 256>>>(
            xc, b_w, c_w, Bmp, Cmp, nullptr, MROWS, 2 * DS, DI);
    }
    // 5) selective scan + D skip + gating (writes y)
    {
        scan_kernel<<<BB * DI / 16, 256>>>(delta, Bmp, Cmp, xc, res,
                                           A_log, Dvec, yb);
    }
    // 6) out_proj: [8192,1024] x [512,1024]^T -> out
    {
        dim3 grid(DM / 64, MROWS / 64);
        gemm_nt<64, 64, 16, 4, 4, 0><<<grid, 256>>>(
            yb, out_w, nullptr, out, nullptr, nullptr, MROWS, DM, DI);
    }
}

// round 2
// speedup vs baseline: 1.6167x; 1.6167x over previous
#include <cuda_runtime.h>
#include <math.h>
#include <stdint.h>

// Problem constants
#define BB 4
#define TTT 2048
#define DM 512
#define DI 1024
#define DS 16
#define DCONV 4
#define MROWS (BB*TTT)   // 8192

// Scratch (allocation-free rule: __device__ globals)
__device__ float g_xs   [(size_t)MROWS*DI];
__device__ float g_res  [(size_t)MROWS*DI];
__device__ float g_xc   [(size_t)MROWS*DI];
__device__ float g_delta[(size_t)MROWS*DI];
__device__ float g_Bm   [(size_t)MROWS*DS];
__device__ float g_Cm   [(size_t)MROWS*DS];
__device__ float g_y    [(size_t)MROWS*DI];

// ---------------------------------------------------------------------------
// tf32 helpers
// ---------------------------------------------------------------------------
__device__ __forceinline__ uint32_t f2tf32(float x) {
    uint32_t r;
    asm("cvt.rna.tf32.f32 %0, %1;" : "=r"(r) : "f"(x));
    return r;
}

__device__ __forceinline__ void mma_tf32(float c[4], const uint32_t a[4],
                                         const uint32_t b[2]) {
    asm volatile(
        "mma.sync.aligned.m16n8k8.row.col.f32.tf32.tf32.f32 "
        "{%0,%1,%2,%3}, {%4,%5,%6,%7}, {%8,%9}, {%0,%1,%2,%3};\n"
        : "+f"(c[0]), "+f"(c[1]), "+f"(c[2]), "+f"(c[3])
        : "r"(a[0]), "r"(a[1]), "r"(a[2]), "r"(a[3]),
          "r"(b[0]), "r"(b[1]));
}

// ---------------------------------------------------------------------------
// TF32 tensor-core NT GEMM:  C[M,N] = A[M,K] * W[N,K]^T  (row-major)
// EPI: 0 plain -> C1
//      1 split: n<N/2 -> C1 else C2                       (in_proj)
//      2 softplus(acc + bias[n]) -> C1                    (dt_proj)
//      3 W concat: rows<16 from B1, else B2; out split    (b/c proj)
// Warp layout: WARPS_M x WARPS_N warps, warp tile WM x WN.
// ---------------------------------------------------------------------------
template<int BM, int BN, int BK, int WM, int WN, int EPI>
__global__ void gemm_tf32(const float* __restrict__ A,
                          const float* __restrict__ B1,
                          const float* __restrict__ B2,
                          float* __restrict__ C1,
                          float* __restrict__ C2,
                          const float* __restrict__ bias,
                          int M, int N, int K)
{
    constexpr int WARPS_M = BM / WM;
    constexpr int WARPS_N = BN / WN;
    constexpr int THREADS = WARPS_M * WARPS_N * 32;
    constexpr int MF = WM / 16;       // 16-row mma fragments per warp
    constexpr int NF = WN / 8;        // 8-col  mma fragments per warp
    constexpr int LDA = BK + 4;

    __shared__ uint32_t As[BM][LDA];
    __shared__ uint32_t Bs[BN][LDA];

    const int tid   = threadIdx.x;
    const int wid   = tid >> 5;
    const int lane  = tid & 31;
    const int g     = lane >> 2;      // group id 0..7
    const int t4    = lane & 3;
    const int wm    = wid % WARPS_M;
    const int wn    = wid / WARPS_M;
    const int m0    = blockIdx.y * BM;
    const int n0    = blockIdx.x * BN;

    float acc[MF][NF][4];
#pragma unroll
    for (int i = 0; i < MF; ++i)
#pragma unroll
        for (int j = 0; j < NF; ++j)
#pragma unroll
            for (int q = 0; q < 4; ++q) acc[i][j][q] = 0.f;

    for (int k0 = 0; k0 < K; k0 += BK) {
        // --- load A tile (BM x BK) as tf32, float4 global loads ---
#pragma unroll 2
        for (int i = tid; i < BM * (BK / 4); i += THREADS) {
            int m  = i / (BK / 4);
            int kq = (i % (BK / 4)) * 4;
            const float4 v = *reinterpret_cast<const float4*>(
                A + (size_t)(m0 + m) * K + k0 + kq);
            As[m][kq + 0] = f2tf32(v.x);
            As[m][kq + 1] = f2tf32(v.y);
            As[m][kq + 2] = f2tf32(v.z);
            As[m][kq + 3] = f2tf32(v.w);
        }
        // --- load W tile (BN x BK) ---
#pragma unroll 2
        for (int i = tid; i < BN * (BK / 4); i += THREADS) {
            int n  = i / (BK / 4);
            int kq = (i % (BK / 4)) * 4;
            int gn = n0 + n;
            const float* Wrow;
            if (EPI == 3) {
                Wrow = (gn < DS) ? (B1 + (size_t)gn * K)
                                 : (B2 + (size_t)(gn - DS) * K);
            } else {
                Wrow = B1 + (size_t)gn * K;
            }
            const float4 v = *reinterpret_cast<const float4*>(Wrow + k0 + kq);
            Bs[n][kq + 0] = f2tf32(v.x);
            Bs[n][kq + 1] = f2tf32(v.y);
            Bs[n][kq + 2] = f2tf32(v.z);
            Bs[n][kq + 3] = f2tf32(v.w);
        }
        __syncthreads();

        // --- mma over BK in steps of 8 ---
#pragma unroll
        for (int kk = 0; kk < BK; kk += 8) {
            uint32_t afrag[MF][4];
            uint32_t bfrag[NF][2];
#pragma unroll
            for (int i = 0; i < MF; ++i) {
                const int r = wm * WM + i * 16 + g;
                afrag[i][0] = As[r    ][kk + t4    ];
                afrag[i][1] = As[r + 8][kk + t4    ];
                afrag[i][2] = As[r    ][kk + t4 + 4];
                afrag[i][3] = As[r + 8][kk + t4 + 4];
            }
#pragma unroll
            for (int j = 0; j < NF; ++j) {
                const int c = wn * WN + j * 8 + g;
                bfrag[j][0] = Bs[c][kk + t4    ];
                bfrag[j][1] = Bs[c][kk + t4 + 4];
            }
#pragma unroll
            for (int i = 0; i < MF; ++i)
#pragma unroll
                for (int j = 0; j < NF; ++j)
                    mma_tf32(acc[i][j], afrag[i], bfrag[j]);
        }
        __syncthreads();
    }

    // --- epilogue ---
#pragma unroll
    for (int i = 0; i < MF; ++i) {
#pragma unroll
        for (int j = 0; j < NF; ++j) {
#pragma unroll
            for (int q = 0; q < 4; ++q) {
                const int r = m0 + wm * WM + i * 16 + g + ((q >= 2) ? 8 : 0);
                const int c = n0 + wn * WN + j * 8 + t4 * 2 + (q & 1);
                float v = acc[i][j][q];
                if (EPI == 0) {
                    C1[(size_t)r * N + c] = v;
                } else if (EPI == 1) {
                    const int half = N / 2;
                    if (c < half) C1[(size_t)r * half + c] = v;
                    else          C2[(size_t)r * half + (c - half)] = v;
                } else if (EPI == 2) {
                    v += bias[c];
                    C1[(size_t)r * N + c] = (v > 20.f) ? v : log1pf(expf(v));
                } else { // EPI == 3
                    if (c < DS) C1[(size_t)r * DS + c] = v;
                    else        C2[(size_t)r * DS + (c - DS)] = v;
                }
            }
        }
    }
}

// ---------------------------------------------------------------------------
// Causal depthwise conv1d (width 4) + bias + SiLU:  g_xs -> g_xc
// ---------------------------------------------------------------------------
__global__ void conv_silu_kernel(const float* __restrict__ xs,
                                 const float* __restrict__ w,   // [DI,1,4]
                                 const float* __restrict__ bias,
                                 float* __restrict__ out)
{
    size_t i = (size_t)blockIdx.x * blockDim.x + threadIdx.x;
    if (i >= (size_t)MROWS * DI) return;
    int d  = (int)(i & (DI - 1));
    int bt = (int)(i >> 10);
    int t  = bt & (TTT - 1);

    float acc = bias[d];
    const float* wd = w + d * DCONV;
#pragma unroll
    for (int k = 0; k < DCONV; ++k) {
        int tt = t - (DCONV - 1) + k;
        if (tt >= 0) acc = fmaf(wd[k], xs[i + (size_t)(tt - t) * DI], acc);
    }
    out[i] = acc * (1.f / (1.f + expf(-acc)));
}

// ---------------------------------------------------------------------------
// Selective scan. 16 lanes per (b,d) channel; lane n owns state h[n].
// Fused: y = (sum_n h*C + x*D) * silu(res)
// ---------------------------------------------------------------------------
__global__ void scan_kernel(const float* __restrict__ delta,
                            const float* __restrict__ Bm,
                            const float* __restrict__ Cm,
                            const float* __restrict__ xc,
                            const float* __restrict__ res,
                            const float* __restrict__ A_log,
                            const float* __restrict__ Dv,
                            float* __restrict__ y)
{
    const int sub = threadIdx.x >> 4;
    const int n   = threadIdx.x & 15;
    const int gch = blockIdx.x * 16 + sub;
    const int b = gch >> 10;
    const int d = gch & (DI - 1);

    const float Acoef = -__expf(A_log[d * DS + n]);
    const float Dval  = Dv[d];

    const size_t rowbase = (size_t)b * TTT;
    const float* dp = delta + rowbase * DI + d;
    const float* xp = xc    + rowbase * DI + d;
    const float* rp = res   + rowbase * DI + d;
    const float* Bp = Bm    + rowbase * DS + n;
    const float* Cp = Cm    + rowbase * DS + n;
    float*       yp = y     + rowbase * DI + d;

    float h = 0.f;
    for (int t = 0; t < TTT; ++t) {
        const size_t od = (size_t)t * DI;
        const size_t os = (size_t)t * DS;
        float dlt = dp[od];
        float xv  = xp[od];
        float Bn  = Bp[os];
        float Cn  = Cp[os];

        float dA = __expf(dlt * Acoef);
        h = fmaf(dA, h, (dlt * Bn) * xv);

        float p = h * Cn;
        p += __shfl_xor_sync(0xffffffffu, p, 8);
        p += __shfl_xor_sync(0xffffffffu, p, 4);
        p += __shfl_xor_sync(0xffffffffu, p, 2);
        p += __shfl_xor_sync(0xffffffffu, p, 1);

        if (n == 0) {
            float r = rp[od];
            float gate = r * (1.f / (1.f + expf(-r)));
            yp[od] = (p + xv * Dval) * gate;
        }
    }
}

// ---------------------------------------------------------------------------
extern "C" void kernel_launch(void* const* d_in, const int* in_sizes, int n_in,
                              void* d_out, int out_size)
{
    const float* x        = (const float*)d_in[0];
    const float* in_w     = (const float*)d_in[1];
    const float* conv_w   = (const float*)d_in[2];
    const float* conv_b   = (const float*)d_in[3];
    const float* b_w      = (const float*)d_in[4];
    const float* c_w      = (const float*)d_in[5];
    const float* dt_w     = (const float*)d_in[6];
    const float* dt_b     = (const float*)d_in[7];
    const float* A_log    = (const float*)d_in[8];
    const float* Dvec     = (const float*)d_in[9];
    const float* out_w    = (const float*)d_in[10];
    float* out            = (float*)d_out;

    float *xs, *res, *xc, *delta, *Bmp, *Cmp, *yb;
    cudaGetSymbolAddress((void**)&xs,    g_xs);
    cudaGetSymbolAddress((void**)&res,   g_res);
    cudaGetSymbolAddress((void**)&xc,    g_xc);
    cudaGetSymbolAddress((void**)&delta, g_delta);
    cudaGetSymbolAddress((void**)&Bmp,   g_Bm);
    cudaGetSymbolAddress((void**)&Cmp,   g_Cm);
    cudaGetSymbolAddress((void**)&yb,    g_y);

    // 1) in_proj: [8192,512] x [2048,512]^T -> split xs/res
    {
        dim3 grid(2 * DI / 128, MROWS / 128);
        gemm_tf32<128, 128, 32, 64, 32, 1><<<grid, 256>>>(
            x, in_w, nullptr, xs, res, nullptr, MROWS, 2 * DI, DM);
    }
    // 2) causal depthwise conv + SiLU
    {
        size_t total = (size_t)MROWS * DI;
        conv_silu_kernel<<<(unsigned)((total + 255) / 256), 256>>>(
            xs, conv_w, conv_b, xc);
    }
    // 3) dt_proj + softplus: [8192,1024] x [1024,1024]^T
    {
        dim3 grid(DI / 128, MROWS / 128);
        gemm_tf32<128, 128, 32, 64, 32, 2><<<grid, 256>>>(
            xc, dt_w, nullptr, delta, nullptr, dt_b, MROWS, DI, DI);
    }
    // 4) B/C proj (concat N=32): [8192,1024] x [32,1024]^T
    {
        dim3 grid(1, MROWS / 128);
        gemm_tf32<128, 32, 32, 16, 32, 3><<<grid, 256>>>(
            xc, b_w, c_w, Bmp, Cmp, nullptr, MROWS, 2 * DS, DI);
    }
    // 5) selective scan + D skip + gating
    {
        scan_kernel<<<BB * DI / 16, 256>>>(delta, Bmp, Cmp, xc, res,
                                           A_log, Dvec, yb);
    }
    // 6) out_proj: [8192,1024] x [512,1024]^T -> out
    {
        dim3 grid(DM / 128, MROWS / 128);
        gemm_tf32<128, 128, 32, 64, 32, 0><<<grid, 256>>>(
            yb, out_w, nullptr, out, nullptr, nullptr, MROWS, DM, DI);
    }
}